// round 16
// baseline (speedup 1.0000x reference)
#include <cuda_runtime.h>
#include <cuda_fp16.h>
#include <cstdint>
#include <cstddef>

#define S_SIZE 4096
#define IN_SZ  2048
#define KTOT   6144
#define BATCH  4096

// ---------------- scratch (device globals; no allocation APIs) ----------------
// g_W rows interleaved: row = (s>>5)*128 + gate*32 + (s&31)
__device__ __half g_W[4ull * S_SIZE * KTOT];
__device__ __half g_Zt[(size_t)BATCH * KTOT];           // [b][k] fp16 K-major

// ---------------- helpers ----------------
__device__ __forceinline__ uint32_t smem_u32(const void* p) {
    return (uint32_t)__cvta_generic_to_shared(p);
}

__device__ __forceinline__ void ldsm_x4(uint32_t& r0, uint32_t& r1, uint32_t& r2, uint32_t& r3,
                                        uint32_t addr) {
    asm volatile("ldmatrix.sync.aligned.m8n8.x4.shared.b16 {%0,%1,%2,%3}, [%4];"
                 : "=r"(r0), "=r"(r1), "=r"(r2), "=r"(r3) : "r"(addr));
}

__device__ __forceinline__ void mma16816(float* d, const uint32_t* a, const uint32_t* b) {
    asm volatile(
        "mma.sync.aligned.m16n8k16.row.col.f32.f16.f16.f32 "
        "{%0,%1,%2,%3}, {%4,%5,%6,%7}, {%8,%9}, {%0,%1,%2,%3};"
        : "+f"(d[0]), "+f"(d[1]), "+f"(d[2]), "+f"(d[3])
        : "r"(a[0]), "r"(a[1]), "r"(a[2]), "r"(a[3]), "r"(b[0]), "r"(b[1]));
}

__device__ __forceinline__ float tanh_fast(float x) {
    float r;
    asm("tanh.approx.f32 %0, %1;" : "=f"(r) : "f"(x));
    return r;
}
__device__ __forceinline__ float sig_fast(float x) {
    return fmaf(tanh_fast(0.5f * x), 0.5f, 0.5f);
}

// ---------------- fused convert: weights (blocks [0, NWB)) + acts (rest) ----------------
#define NWB 4096
#define ACT_KB (KTOT / 32)               // 192

__global__ void convert_fused(const float* __restrict__ wf_in, const float* __restrict__ wf_h,
                              const float* __restrict__ wi_in, const float* __restrict__ wi_h,
                              const float* __restrict__ wc_in, const float* __restrict__ wc_h,
                              const float* __restrict__ wo_in, const float* __restrict__ wo_h,
                              const float* __restrict__ x, const float* __restrict__ h) {
    if (blockIdx.x < NWB) {
        // ---- weight packing: 8 k-elems per step, gate-interleaved destination rows ----
        const int per_gate8 = S_SIZE * (KTOT / 8);          // 3145728
        const int total8 = 4 * per_gate8;
        const int nthr = NWB * 256;
        for (int t = blockIdx.x * blockDim.x + threadIdx.x; t < total8; t += nthr) {
            int g = t / per_gate8;
            int rem = t - g * per_gate8;
            int s = rem / (KTOT / 8);                       // /768
            int k = (rem - s * (KTOT / 8)) * 8;
            const float* win = (g == 0) ? wf_in : (g == 1) ? wi_in : (g == 2) ? wc_in : wo_in;
            const float* wh  = (g == 0) ? wf_h  : (g == 1) ? wi_h  : (g == 2) ? wc_h  : wo_h;
            float4 v0, v1;
            if (k < IN_SZ) {
                const float* p = win + (size_t)s * IN_SZ + k;
                v0 = *(const float4*)p;
                v1 = *(const float4*)(p + 4);
            } else {
                const float* p = wh + (size_t)s * S_SIZE + (k - IN_SZ);
                v0 = *(const float4*)p;
                v1 = *(const float4*)(p + 4);
            }
            __half2 h0 = __floats2half2_rn(v0.x, v0.y);
            __half2 h1 = __floats2half2_rn(v0.z, v0.w);
            __half2 h2 = __floats2half2_rn(v1.x, v1.y);
            __half2 h3 = __floats2half2_rn(v1.z, v1.w);
            uint4 pack;
            pack.x = *(uint32_t*)&h0; pack.y = *(uint32_t*)&h1;
            pack.z = *(uint32_t*)&h2; pack.w = *(uint32_t*)&h3;
            int row = ((s >> 5) << 7) + (g << 5) + (s & 31);    // gate-interleaved
            *(uint4*)(g_W + (size_t)row * KTOT + k) = pack;
        }
    } else {
        // ---- activation transpose ----
        __shared__ float tile[32][33];
        const int bid = blockIdx.x - NWB;
        const int kb = (bid % ACT_KB) * 32;
        const int bb = (bid / ACT_KB) * 32;
        const int tx = threadIdx.x & 31;
        const int ty = threadIdx.x >> 5;            // 0..7
#pragma unroll
        for (int i = 0; i < 4; i++) {
            int k = kb + ty + i * 8;
            const float* src = (k < IN_SZ) ? (x + (size_t)k * BATCH)
                                           : (h + (size_t)(k - IN_SZ) * BATCH);
            tile[ty + i * 8][tx] = src[bb + tx];
        }
        __syncthreads();
#pragma unroll
        for (int i = 0; i < 4; i++) {
            int b = bb + ty + i * 8;
            int k = kb + tx;
            g_Zt[(size_t)b * KTOT + k] = __float2half_rn(tile[tx][ty + i * 8]);
        }
    }
}

// ---------------- GEMM + fused LSTM epilogue ----------------
// CTA 128x128, 128 threads, 4 warps 2(m) x 2(n), warp tile 64x64, occupancy 2.
// One CTA = all 4 gates of a 32(state-rows) x 128(batch) patch.
#define KBLK        64
#define NUM_IT      (KTOT / KBLK)        // 96
#define STAGE_BYTES 32768
#define NSTAGE      3
#define SMEM_TOTAL  (NSTAGE * STAGE_BYTES)
#define EPI_STRIDE  136                  // fp16 units; 34 KB epi buffer, conflict-free

__device__ __forceinline__ void fill_stage(uint32_t sbase, const __half* Ag, const __half* Bg,
                                           int kblk, int tid) {
#pragma unroll
    for (int i = 0; i < 16; i++) {
        int id = i * 128 + tid;
        int op = id >> 10;               // 0 = A, 1 = B
        int r  = (id >> 3) & 127;
        int c  = id & 7;
        const __half* src = (op ? Bg : Ag) + (size_t)r * KTOT + kblk + c * 8;
        uint32_t dst = sbase + (uint32_t)op * 16384u + (uint32_t)r * 128u
                     + (uint32_t)((c ^ (r & 7)) * 16);
        asm volatile("cp.async.cg.shared.global [%0], [%1], 16;\n"
                     :: "r"(dst), "l"(src) : "memory");
    }
    asm volatile("cp.async.commit_group;\n" ::: "memory");
}

__global__ void __launch_bounds__(128, 2) lstm_gemm(
    const float* __restrict__ prev_state,
    const float* __restrict__ bfp, const float* __restrict__ bip,
    const float* __restrict__ bcp, const float* __restrict__ bop,
    float* __restrict__ out)
{
    extern __shared__ __align__(1024) char smem[];
    const uint32_t sb0 = smem_u32(smem);
    const int tid = threadIdx.x;
    const int wid = tid >> 5, l = tid & 31;
    const int wm = wid >> 1, wn = wid & 1;          // 2x2 warps, warp tile 64x64
    const int m0 = (int)blockIdx.y * 128;           // over 16384 (interleaved rows)
    const int n0 = (int)blockIdx.x * 128;           // over 4096

    const __half* Ag = g_W  + (size_t)m0 * KTOT;
    const __half* Bg = g_Zt + (size_t)n0 * KTOT;

    int arow[4], brow[4];
#pragma unroll
    for (int t = 0; t < 4; t++)
        arow[t] = wm * 64 + t * 16 + (l & 7) + ((l >> 3) & 1) * 8;
#pragma unroll
    for (int p = 0; p < 4; p++)
        brow[p] = wn * 64 + p * 16 + (l & 7) + ((l >> 4) & 1) * 8;
    const int a_sel = (l >> 4) & 1;
    const int b_sel = (l >> 3) & 1;

    float acc[4][8][4];
#pragma unroll
    for (int t = 0; t < 4; t++)
#pragma unroll
        for (int p = 0; p < 8; p++)
#pragma unroll
            for (int q = 0; q < 4; q++) acc[t][p][q] = 0.0f;

    fill_stage(sb0, Ag, Bg, 0, tid);
    fill_stage(sb0 + STAGE_BYTES, Ag, Bg, KBLK, tid);

    for (int it = 0; it < NUM_IT; it++) {
        if (it == NUM_IT - 1) asm volatile("cp.async.wait_group 0;\n" ::: "memory");
        else                  asm volatile("cp.async.wait_group 1;\n" ::: "memory");
        __syncthreads();
        if (it + 2 < NUM_IT)
            fill_stage(sb0 + (uint32_t)((it + 2) % NSTAGE) * STAGE_BYTES,
                       Ag, Bg, (it + 2) * KBLK, tid);
        const uint32_t sa = sb0 + (uint32_t)(it % NSTAGE) * STAGE_BYTES;
        const uint32_t sbq = sa + 16384u;
#pragma unroll
        for (int ks = 0; ks < 4; ks++) {
            uint32_t a[4][4], b[4][4];
#pragma unroll
            for (int t = 0; t < 4; t++) {
                uint32_t addr = sa + (uint32_t)arow[t] * 128u
                              + (uint32_t)(((ks * 2 + a_sel) ^ (arow[t] & 7)) * 16);
                ldsm_x4(a[t][0], a[t][1], a[t][2], a[t][3], addr);
            }
#pragma unroll
            for (int p = 0; p < 4; p++) {
                uint32_t addr = sbq + (uint32_t)brow[p] * 128u
                              + (uint32_t)(((ks * 2 + b_sel) ^ (brow[p] & 7)) * 16);
                ldsm_x4(b[p][0], b[p][1], b[p][2], b[p][3], addr);
            }
#pragma unroll
            for (int t = 0; t < 4; t++)
#pragma unroll
                for (int p = 0; p < 8; p++)
                    mma16816(acc[t][p], a[t], &b[p >> 1][(p & 1) * 2]);
        }
    }

    // ---- fused epilogue: exchange gates through smem, combine, write out ----
    __syncthreads();                      // main-loop smem reads done; reuse buffers
    __half* epi = (__half*)smem;          // [128 rows][EPI_STRIDE]
    const int g  = l >> 2;
    const int tg = l & 3;
#pragma unroll
    for (int t = 0; t < 4; t++) {
#pragma unroll
        for (int p = 0; p < 8; p++) {
            int row = wm * 64 + t * 16 + g;
            int col = wn * 64 + p * 8 + tg * 2;
            *(__half2*)&epi[row * EPI_STRIDE + col] =
                __floats2half2_rn(acc[t][p][0], acc[t][p][1]);
            *(__half2*)&epi[(row + 8) * EPI_STRIDE + col] =
                __floats2half2_rn(acc[t][p][2], acc[t][p][3]);
        }
    }
    __syncthreads();

    // CTA patch: state rows sblk..sblk+31, batch cols n0..n0+127.
    // Within the 128 m-rows: gate q at rows q*32 + s_loc.
    const size_t SB = (size_t)S_SIZE * BATCH;
    const int sloc = tid >> 2;            // 0..31
    const int nb   = (tid & 3) * 32;      // 32 batch cols per thread
    const int sg   = (int)blockIdx.y * 32 + sloc;
    const float vbf = bfp[sg], vbi = bip[sg], vbc = bcp[sg], vbo = bop[sg];
    const float* ps = prev_state + (size_t)sg * BATCH + n0 + nb;
    float* o_ns = out + (size_t)sg * BATCH + n0 + nb;
    float* o_o  = out + SB + (size_t)sg * BATCH + n0 + nb;
    const __half* ef = epi + (size_t)sloc * EPI_STRIDE + nb;
    const __half* ei = ef + 32 * EPI_STRIDE;
    const __half* ec = ef + 64 * EPI_STRIDE;
    const __half* eo = ef + 96 * EPI_STRIDE;
#pragma unroll
    for (int j = 0; j < 32; j += 4) {
        float2 f01 = __half22float2(*(const __half2*)&ef[j]);
        float2 f23 = __half22float2(*(const __half2*)&ef[j + 2]);
        float2 i01 = __half22float2(*(const __half2*)&ei[j]);
        float2 i23 = __half22float2(*(const __half2*)&ei[j + 2]);
        float2 c01 = __half22float2(*(const __half2*)&ec[j]);
        float2 c23 = __half22float2(*(const __half2*)&ec[j + 2]);
        float2 o01 = __half22float2(*(const __half2*)&eo[j]);
        float2 o23 = __half22float2(*(const __half2*)&eo[j + 2]);
        float4 cp = *(const float4*)(ps + j);
        float zf[4] = {f01.x, f01.y, f23.x, f23.y};
        float zi[4] = {i01.x, i01.y, i23.x, i23.y};
        float zc[4] = {c01.x, c01.y, c23.x, c23.y};
        float zo[4] = {o01.x, o01.y, o23.x, o23.y};
        float cpv[4] = {cp.x, cp.y, cp.z, cp.w};
        float nsv[4], ov[4];
#pragma unroll
        for (int q = 0; q < 4; q++) {
            float f  = sig_fast(zf[q] + vbf);
            float ig = sig_fast(zi[q] + vbi);
            float ct = tanh_fast(zc[q] + vbc);
            float og = sig_fast(zo[q] + vbo);
            float ns = fmaf(cpv[q], f, ig * ct);
            nsv[q] = ns;
            ov[q]  = tanh_fast(ns) * og;
        }
        *(float4*)(o_ns + j) = make_float4(nsv[0], nsv[1], nsv[2], nsv[3]);
        *(float4*)(o_o  + j) = make_float4(ov[0], ov[1], ov[2], ov[3]);
    }
}

// ---------------- host ----------------
extern "C" void kernel_launch(void* const* d_in, const int* in_sizes, int n_in,
                              void* d_out, int out_size) {
    const float* input      = (const float*)d_in[0];
    const float* prev_out   = (const float*)d_in[1];
    const float* prev_state = (const float*)d_in[2];
    const float* W_in_f = (const float*)d_in[3];
    const float* W_h_f  = (const float*)d_in[4];
    const float* b_f    = (const float*)d_in[5];
    const float* W_in_i = (const float*)d_in[6];
    const float* W_h_i  = (const float*)d_in[7];
    const float* b_i    = (const float*)d_in[8];
    const float* W_C_i  = (const float*)d_in[9];
    const float* W_C_h  = (const float*)d_in[10];
    const float* b_C    = (const float*)d_in[11];
    const float* W_in_o = (const float*)d_in[12];
    const float* W_h_o  = (const float*)d_in[13];
    const float* b_o    = (const float*)d_in[14];

    static bool attr_set = false;
    if (!attr_set) {
        cudaFuncSetAttribute(lstm_gemm, cudaFuncAttributeMaxDynamicSharedMemorySize, SMEM_TOTAL);
        attr_set = true;
    }

    convert_fused<<<NWB + ACT_KB * (BATCH / 32), 256>>>(
        W_in_f, W_h_f, W_in_i, W_h_i, W_C_i, W_C_h, W_in_o, W_h_o, input, prev_out);
    lstm_gemm<<<dim3(BATCH / 128, 4 * S_SIZE / 128), 128, SMEM_TOTAL>>>(
        prev_state, b_f, b_i, b_C, b_o, (float*)d_out);
}